// round 17
// baseline (speedup 1.0000x reference)
#include <cuda_runtime.h>
#include <math.h>

#define BB    16
#define TT    50
#define GG    64
#define NA    3
#define NC    80
#define CELLS (BB*NA*GG*GG)      // 196608
#define NTGT  (BB*TT)            // 800
#define PLANE 4096               // GG*GG
#define NBLK  148                // one block per SM, single wave, all SMs
#define NT    352                // 11 warps; 148*352 = 52096 >= 49152 dense float4s
#define DENSE_T 49152
#define FULL  0xFFFFFFFFu

// Anchors / 8 (grid units)
__constant__ float c_aw[9] = {1.25f, 2.0f, 4.125f, 3.75f, 7.75f, 7.375f, 14.5f, 19.5f, 46.625f};
__constant__ float c_ah[9] = {1.625f, 3.75f, 2.875f, 7.625f, 5.625f, 14.875f, 11.25f, 24.75f, 40.75f};

// g_acc: 0 bbox, 1 obj_num, 2 zcorr, 3 cls_num, 4 n_obj, 5 clr_sp, 6 n_clr, 7 dense_sp
// Reset by finalize at end of each call (first call: static zero-init) -> replay-clean.
__device__ float g_acc[8];
__device__ int   g_bcount;

__device__ __forceinline__ float softplusf(float z) {
    return fmaxf(z, 0.0f) + __logf(1.0f + __expf(-fabsf(z)));
}
__device__ __forceinline__ float sigmf(float z) { return 1.0f / (1.0f + __expf(-z)); }

__global__ void __launch_bounds__(NT) k_all(const float* __restrict__ bb,
                                            const float* __restrict__ gt,
                                            float* __restrict__ out) {
    __shared__ float s_red[8];

    const int bid = blockIdx.x, tid = threadIdx.x, lane = tid & 31;
    const int wib = tid >> 5;                      // warp in block (0..10)
    const int e_t = wib * NBLK + bid;              // target id for this warp
    const bool is_tw = (e_t < NTGT);

    if (tid < 8) s_red[tid] = 0.0f;

    // ========== ISSUE ALL INDEPENDENT LOADS UP FRONT (dense + gt) ============
    const int di = bid * NT + tid;
    const bool has_dense = (di < DENSE_T);
    float4 v = make_float4(0.f, 0.f, 0.f, 0.f);
    if (has_dense) {
        int plane = di >> 10;
        int pos   = (di & 1023) << 2;
        int b = plane / NA, a = plane % NA;
        v = *(const float4*)(bb + ((size_t)b * 255 + a * 85 + 4) * PLANE + pos);
    }
    // gt rows for target warps (2 slots per lane) — overlaps the dense round trip
    float R[2][5];
    int   b_tw = 0, t0 = 0;
    if (is_tw) {
        b_tw = e_t / TT;
        t0   = e_t % TT;
        const float* gtb = gt + b_tw * TT * 5;
        #pragma unroll
        for (int j = 0; j < 2; j++) {
            int tj = lane + 32 * j;
            if (tj < TT) {
                const float* r = gtb + tj * 5;
                R[j][0] = r[0]; R[j][1] = r[1]; R[j][2] = r[2];
                R[j][3] = r[3]; R[j][4] = r[4];
            } else {
                R[j][0] = R[j][1] = R[j][2] = R[j][3] = R[j][4] = 0.0f;
            }
        }
    }

    __syncthreads();   // s_red zero visible; loads stay in flight

    // ---------------- DENSE: softplus-sum (consumes v) -----------------------
    {
        float dsum = 0.0f;
        if (has_dense) {
            float h  = fmaxf(v.x, 0.0f) + fmaxf(v.y, 0.0f) + fmaxf(v.z, 0.0f) + fmaxf(v.w, 0.0f);
            float e0 = __expf(-fabsf(v.x));
            float e1 = __expf(-fabsf(v.y));
            float e2 = __expf(-fabsf(v.z));
            float e3 = __expf(-fabsf(v.w));
            dsum = h + __logf(((1.0f + e0) * (1.0f + e1)) * ((1.0f + e2) * (1.0f + e3)));
        }
        #pragma unroll
        for (int off = 16; off > 0; off >>= 1)
            dsum += __shfl_down_sync(FULL, dsum, off);
        if (lane == 0 && dsum != 0.0f) atomicAdd(&s_red[7], dsum);
    }

    // ---------------- TARGET WARPS (gt already in registers) -----------------
    if (is_tw) {
        const int b = b_tw;

        int   pv_[2]   = {-1, -1};   // pos | (clr<<12), -1 if invalid
        int   cell_[2] = {-1, -1};
        int   cls_[2]  = {0, 0};
        int   best_[2] = {0, 0};
        float GX[2], GY[2], GW_[2], GH[2];

        #pragma unroll
        for (int j = 0; j < 2; j++) {
            float x = R[j][0], y = R[j][1], w = R[j][2], h = R[j][3], c = R[j][4];
            if ((x + y + w + h + c) > 0.0f) {
                float gx = x * GG, gy = y * GG, gwf = w * GG, ghf = h * GG;
                int gi = (int)gy, gj = (int)gx;
                if (gi >= 0 && gi < GG && gj >= 0 && gj < GG) {
                    int pos = gi * GG + gj;
                    float bi = -1.0f; int bst = 0, clr = 0;
                    #pragma unroll
                    for (int a = 0; a < 9; a++) {
                        float inter = fminf(gwf, c_aw[a]) * fminf(ghf, c_ah[a]);
                        float uni   = gwf * ghf + c_aw[a] * c_ah[a] - inter;
                        float iou   = inter / (uni + 1e-16f);
                        if (a >= 6 && iou > 0.5f) clr |= 1 << (a - 6);
                        if (iou > bi) { bi = iou; bst = a; }
                    }
                    pv_[j]   = pos | (clr << 12);
                    best_[j] = bst;
                    if (bst >= 6) cell_[j] = (bst - 6) * PLANE + pos;
                    cls_[j] = (int)c;
                    GX[j] = gx; GY[j] = gy; GW_[j] = gwf; GH[j] = ghf;
                }
            }
        }

        const int srcl = t0 & 31, srcs = t0 >> 5;   // warp-uniform
        int vsel = srcs ? pv_[1]   : pv_[0];
        int csel = srcs ? cell_[1] : cell_[0];
        const int vt0     = __shfl_sync(FULL, vsel, srcl);
        const int cell_t0 = __shfl_sync(FULL, csel, srcl);
        const int pos_t0  = (vt0 >= 0) ? (vt0 & 4095) : -1;
        const int clr_t0  = (vt0 >= 0) ? ((vt0 >> 12) & 7) : 0;

        // ======== ISSUE ALL GATHER LOADS NOW (overlap with votes below) ======
        const bool hit = (cell_t0 >= 0);            // warp-uniform
        const int  a_win = hit ? (cell_t0 >> 12) : 0;
        const int  ij    = hit ? (cell_t0 & (PLANE - 1)) : 0;
        const float* base = bb + ((size_t)b * 255 + a_win * 85) * PLANE + ij;
        float zh = 0.0f, za = 0.0f, zb = 0.0f, zc = 0.0f;
        if (hit) {
            zh = (lane < 5)  ? base[lane * PLANE]        : 0.0f;
            za = base[(5 + lane) * PLANE];
            zb = base[(37 + lane) * PLANE];
            zc = (lane < 16) ? base[(69 + lane) * PLANE] : 0.0f;
        }
        const bool myclr = (lane < 3) && ((clr_t0 >> lane) & 1);
        float zclr = 0.0f;
        if (myclr) zclr = bb[((size_t)b * 255 + lane * 85 + 4) * PLANE + pos_t0];

        // ======== RESOLUTION (runs while gathers are in flight) ==============
        int pvpos[2], clrb[2];
        pvpos[0] = (pv_[0] >= 0) ? (pv_[0] & 4095) : -2;
        pvpos[1] = (pv_[1] >= 0) ? (pv_[1] & 4095) : -2;
        clrb[0]  = (pv_[0] >= 0) ? (pv_[0] >> 12) & 7 : 0;
        clrb[1]  = (pv_[1] >= 0) ? (pv_[1] >> 12) & 7 : 0;
        int owned[3], cellcleared[3];
        #pragma unroll
        for (int a = 0; a < 3; a++) {
            unsigned m0 = __ballot_sync(FULL, ((clrb[0] >> a) & 1) && (pvpos[0] == pos_t0));
            unsigned m1 = __ballot_sync(FULL, ((clrb[1] >> a) & 1) && (pvpos[1] == pos_t0));
            cellcleared[a] = (m0 | m1) != 0u;
            int omin = m0 ? (__ffs(m0) - 1) : (m1 ? (32 + __ffs(m1) - 1) : 64);
            owned[a] = ((clr_t0 >> a) & 1) && (omin == t0);
        }

        unsigned w0 = __ballot_sync(FULL, (cell_[0] >= 0) && (cell_[0] == cell_t0));
        unsigned w1 = __ballot_sync(FULL, (cell_[1] >= 0) && (cell_[1] == cell_t0));
        int mx = w1 ? (32 + 31 - __clz(w1)) : (w0 ? (31 - __clz(w0)) : -1);
        const bool winner = hit && (mx == t0);      // warp-uniform

        unsigned cb0 = 0, cb1 = 0, cb2 = 0;
        #pragma unroll
        for (int j = 0; j < 2; j++) {
            if (cell_[j] >= 0 && cell_[j] == cell_t0) {
                int c = cls_[j];
                if (c < 32)      cb0 |= 1u << c;
                else if (c < 64) cb1 |= 1u << (c - 32);
                else             cb2 |= 1u << (c - 64);
            }
        }
        #pragma unroll
        for (int off = 16; off > 0; off >>= 1) {
            cb0 |= __shfl_xor_sync(FULL, cb0, off);
            cb1 |= __shfl_xor_sync(FULL, cb1, off);
            cb2 |= __shfl_xor_sync(FULL, cb2, off);
        }

        if (myclr && owned[lane]) {
            atomicAdd(&s_red[5], softplusf(zclr));
            atomicAdd(&s_red[6], 1.0f);
        }

        if (winner) {
            const bool cleared = cellcleared[a_win] != 0;

            float h2  = fmaxf(za, 0.0f) + fmaxf(zb, 0.0f);
            float ea  = __expf(-fabsf(za));
            float eb  = __expf(-fabsf(zb));
            float cls = h2 + __logf((1.0f + ea) * (1.0f + eb))
                      - (float)((cb0 >> lane) & 1u) * za
                      - (float)((cb1 >> lane) & 1u) * zb;
            if (lane < 16) cls += softplusf(zc) - (float)((cb2 >> lane) & 1u) * zc;
            #pragma unroll
            for (int off = 16; off > 0; off >>= 1)
                cls += __shfl_down_sync(FULL, cls, off);
            if (lane == 0) atomicAdd(&s_red[3], cls);

            float gxs = srcs ? GX[1]  : GX[0];
            float gys = srcs ? GY[1]  : GY[0];
            float gws = srcs ? GW_[1] : GW_[0];
            float ghs = srcs ? GH[1]  : GH[0];
            int   bss = srcs ? best_[1] : best_[0];
            float gxb = __shfl_sync(FULL, gxs, srcl);
            float gyb = __shfl_sync(FULL, gys, srcl);
            float gwb = __shfl_sync(FULL, gws, srcl);
            float ghb = __shfl_sync(FULL, ghs, srcl);
            int   bsb = __shfl_sync(FULL, bss, srcl);

            if (lane == 0) {
                float tx = gxb - (float)(int)gxb;
                float sx = sigmf(zh);
                atomicAdd(&s_red[0], (sx - tx) * (sx - tx));
            } else if (lane == 1) {
                float ty = gyb - (float)(int)gyb;
                float sy = sigmf(zh);
                atomicAdd(&s_red[0], (sy - ty) * (sy - ty));
            } else if (lane == 2) {
                float tw = __logf(gwb / c_aw[bsb] + 1e-16f);
                atomicAdd(&s_red[0], (zh - tw) * (zh - tw));
            } else if (lane == 3) {
                float th = __logf(ghb / c_ah[bsb] + 1e-16f);
                atomicAdd(&s_red[0], (zh - th) * (zh - th));
            } else if (lane == 4) {
                atomicAdd(&s_red[1], softplusf(zh) - zh);   // obj numerator
                if (!cleared) atomicAdd(&s_red[2], zh);     // noobj z-correction
                atomicAdd(&s_red[4], 1.0f);                 // n_obj
            }
        }
    }

    // ---------------- block -> global accumulate, then finalize --------------
    __syncthreads();
    if (tid < 8) {
        float vv = s_red[tid];
        if (vv != 0.0f) atomicAdd(&g_acc[tid], vv);
        __threadfence();
    }
    __syncthreads();
    if (tid == 0) {
        int old = atomicAdd(&g_bcount, 1);
        if (old == NBLK - 1) {
            __threadfence();
            float n_obj   = fmaxf(g_acc[4], 1.0f);
            float n_noobj = fmaxf((float)CELLS - g_acc[6], 1.0f);
            float noobj_num = g_acc[7] - g_acc[5] - g_acc[2];
            float bbox = 5.0f * g_acc[0] / n_obj;
            float obj  = g_acc[1] / n_obj + 0.5f * noobj_num / n_noobj;
            float cls  = g_acc[3] / (n_obj * (float)NC);
            out[0] = bbox + obj + cls;
            out[1] = bbox;
            out[2] = obj;
            out[3] = cls;
            #pragma unroll
            for (int k = 0; k < 8; k++) g_acc[k] = 0.0f;
            g_bcount = 0;
        }
    }
}

// ---------------------------------------------------------------------------
extern "C" void kernel_launch(void* const* d_in, const int* in_sizes, int n_in,
                              void* d_out, int out_size) {
    const float* backbone = (const float*)d_in[0];  // [16, 255, 64, 64] f32
    const float* gt       = (const float*)d_in[1];  // [16, 50, 5] f32
    float* out            = (float*)d_out;          // 4 f32

    k_all<<<NBLK, NT>>>(backbone, gt, out);
}